// round 2
// baseline (speedup 1.0000x reference)
#include <cuda_runtime.h>
#include <cuda_bf16.h>

#define B_     8
#define N_     2048
#define FIN    128
#define FOUT   64
#define ALPHA  0.2f

// Scratch (device globals — no allocation allowed)
__device__ float g_Wh[B_ * N_ * FOUT];   // 4 MB
__device__ float g_f[B_ * N_];
__device__ float g_g[B_ * N_];

// ---------------------------------------------------------------------------
// Kernel 1: Wh = h @ W ; f = Wh @ a1 ; g = Wh @ a2
// 256 threads, 4 rows per block. thread (r = tid/64, fc = tid%64) owns Wh[r][fc].
// ---------------------------------------------------------------------------
__global__ void __launch_bounds__(256) k_wh(const float* __restrict__ h,
                                            const float* __restrict__ W,
                                            const float* __restrict__ a) {
    const int ROWS = 4;
    __shared__ float h_s[ROWS][FIN];
    __shared__ float red[8][2];

    int row0 = blockIdx.x * ROWS;       // global row index in [0, B*N)
    int tid  = threadIdx.x;
    int r    = tid >> 6;                // 0..3
    int fc   = tid & 63;                // 0..63

    // load 4 rows of h (coalesced)
    #pragma unroll
    for (int l = 0; l < 2; l++) {
        int idx = tid + l * 256;        // 0..511
        int rr = idx >> 7, k = idx & 127;
        h_s[rr][k] = h[(size_t)(row0 + rr) * FIN + k];
    }
    __syncthreads();

    float acc = 0.f;
    #pragma unroll 8
    for (int k = 0; k < FIN; k++)
        acc = fmaf(h_s[r][k], W[k * FOUT + fc], acc);

    g_Wh[(size_t)(row0 + r) * FOUT + fc] = acc;

    float pf = acc * a[fc];
    float pg = acc * a[FOUT + fc];
    #pragma unroll
    for (int off = 16; off > 0; off >>= 1) {
        pf += __shfl_down_sync(0xffffffffu, pf, off);
        pg += __shfl_down_sync(0xffffffffu, pg, off);
    }
    int wid = tid >> 5;
    if ((tid & 31) == 0) { red[wid][0] = pf; red[wid][1] = pg; }
    __syncthreads();
    if (tid < ROWS) {
        g_f[row0 + tid] = red[2 * tid][0] + red[2 * tid + 1][0];
        g_g[row0 + tid] = red[2 * tid][1] + red[2 * tid + 1][1];
    }
}

// ---------------------------------------------------------------------------
// Kernel 2: fused masked-softmax attention + att@Wh   (flash style, no max
// subtraction — exponent range is provably safe in fp32 for this problem)
// Block: 256 threads, TI=32 output rows, loops over j in TJ=64 tiles.
// Thread (ig = tid/64, fc = tid%64) owns rows ig*8..ig*8+7, feature fc.
// ---------------------------------------------------------------------------
#define TI 32
#define TJ 64
#define PS 68   // padded p_s row stride (floats): 16B-aligned rows, rowsum reads ok

__global__ void __launch_bounds__(256) k_attn(const float* __restrict__ adj,
                                              float* __restrict__ out) {
    __shared__ float Wh_s[TJ][FOUT];    // 16 KB
    __shared__ float p_s[TI][PS];       // 8.5 KB
    __shared__ float g_s[TJ];
    __shared__ float f_s[TI];
    __shared__ float rowsum[TI];

    int b   = blockIdx.y;
    int i0  = blockIdx.x * TI;
    int tid = threadIdx.x;
    int fc  = tid & 63;                 // feature column
    int ig  = tid >> 6;                 // row group 0..3

    const float* Wh_b = g_Wh + (size_t)b * N_ * FOUT;

    if (tid < TI) {
        f_s[tid]    = g_f[b * N_ + i0 + tid];
        rowsum[tid] = 0.f;
    }

    float acc[8];
    #pragma unroll
    for (int r = 0; r < 8; r++) acc[r] = 0.f;

    for (int jt = 0; jt < N_ / TJ; jt++) {
        int j0 = jt * TJ;
        __syncthreads();   // protect p_s/Wh_s readers of previous tile (+init)

        // load Wh tile (64x64) as float4, coalesced
        #pragma unroll
        for (int l = 0; l < 4; l++) {
            int idx = tid + l * 256;            // 0..1023 float4 slots
            int row = idx >> 4, c4 = idx & 15;
            float4 v = *(const float4*)&Wh_b[(size_t)(j0 + row) * FOUT + c4 * 4];
            *(float4*)&Wh_s[row][c4 * 4] = v;
        }
        if (tid < TJ) g_s[tid] = g_g[b * N_ + j0 + tid];
        __syncthreads();

        // score phase: p = adj>0 ? exp(lrelu(f_i + g_j)) : 0
        #pragma unroll
        for (int pass = 0; pass < 8; pass++) {
            int ii = ig * 8 + pass;
            float aij = adj[(size_t)(i0 + ii) * N_ + j0 + fc];
            float v = f_s[ii] + g_s[fc];
            v = v > 0.f ? v : ALPHA * v;
            float p = (aij > 0.f) ? __expf(v) : 0.f;
            p_s[ii][fc] = p;
        }
        __syncthreads();

        // row sums of this tile
        if (tid < TI) {
            float s = 0.f;
            #pragma unroll 8
            for (int jj = 0; jj < TJ; jj++) s += p_s[tid][jj];
            rowsum[tid] += s;
        }

        // accumulate: acc[r] += sum_jj p[ii][jj] * Wh_s[jj][fc]
        // register-block 8 jj at a time: w[8] cached, p via float4 broadcasts
        #pragma unroll 2
        for (int jb = 0; jb < TJ; jb += 8) {
            float w[8];
            #pragma unroll
            for (int q = 0; q < 8; q++) w[q] = Wh_s[jb + q][fc];
            #pragma unroll
            for (int r = 0; r < 8; r++) {
                const float4 pA = *(const float4*)&p_s[ig * 8 + r][jb];
                const float4 pB = *(const float4*)&p_s[ig * 8 + r][jb + 4];
                float t = acc[r];
                t = fmaf(pA.x, w[0], t);
                t = fmaf(pA.y, w[1], t);
                t = fmaf(pA.z, w[2], t);
                t = fmaf(pA.w, w[3], t);
                t = fmaf(pB.x, w[4], t);
                t = fmaf(pB.y, w[5], t);
                t = fmaf(pB.z, w[6], t);
                t = fmaf(pB.w, w[7], t);
                acc[r] = t;
            }
        }
    }
    __syncthreads();  // rowsum of last tile complete

    float* out_b = out + (size_t)b * N_ * FOUT;
    #pragma unroll
    for (int r = 0; r < 8; r++) {
        int ii = ig * 8 + r;
        out_b[(size_t)(i0 + ii) * FOUT + fc] = acc[r] / rowsum[ii];
    }
}

// ---------------------------------------------------------------------------
extern "C" void kernel_launch(void* const* d_in, const int* in_sizes, int n_in,
                              void* d_out, int out_size) {
    const float* h   = (const float*)d_in[0];
    const float* adj = (const float*)d_in[1];
    const float* W   = (const float*)d_in[2];
    const float* a   = (const float*)d_in[3];
    float* out = (float*)d_out;

    k_wh<<<(B_ * N_) / 4, 256>>>(h, W, a);

    dim3 grid(N_ / TI, B_);
    k_attn<<<grid, 256>>>(adj, out);
}

// round 3
// speedup vs baseline: 1.1699x; 1.1699x over previous
#include <cuda_runtime.h>
#include <cuda_bf16.h>

#define B_     8
#define N_     2048
#define FIN    128
#define FOUT   64
#define ALPHA  0.2f

// Scratch (device globals — no allocation allowed)
__device__ float g_Wh[B_ * N_ * FOUT];   // 4 MB
__device__ float g_f[B_ * N_];
__device__ float g_g[B_ * N_];

// ---------------------------------------------------------------------------
// packed fp32x2 helpers (sm_100+ PTX; ptxas never emits FFMA2 from C++)
// ---------------------------------------------------------------------------
__device__ __forceinline__ unsigned long long fma2(unsigned long long a,
                                                   unsigned long long b,
                                                   unsigned long long c) {
    unsigned long long d;
    asm("fma.rn.f32x2 %0, %1, %2, %3;" : "=l"(d) : "l"(a), "l"(b), "l"(c));
    return d;
}
__device__ __forceinline__ unsigned long long pack2(float p) {
    unsigned long long d;
    asm("mov.b64 %0, {%1, %1};" : "=l"(d) : "r"(__float_as_uint(p)));
    return d;
}

// ---------------------------------------------------------------------------
// Kernel 1: Wh = h @ W ; f = Wh @ a1 ; g = Wh @ a2
// 256 threads, 16 rows/block. W cached in shared (transposed, float4 k-chunks).
// thread: fc = tid&63 (one col), rg = tid>>6 -> rows rg*4 .. rg*4+3
// ---------------------------------------------------------------------------
__global__ void __launch_bounds__(256) k_wh(const float* __restrict__ h,
                                            const float* __restrict__ W,
                                            const float* __restrict__ a) {
    __shared__ __align__(16) float W_t[FOUT][FIN + 4];  // transposed, stride 132
    __shared__ __align__(16) float h_s[16][FIN];
    __shared__ float red[16][2][2];

    int row0 = blockIdx.x * 16;
    int tid  = threadIdx.x;
    int fc   = tid & 63;
    int rg   = tid >> 6;          // 0..3

    // load W transposed: 8192 elems / 256 threads = 32 each (coalesced LDG)
    #pragma unroll 8
    for (int l = 0; l < 32; l++) {
        int idx = tid + l * 256;
        int k = idx >> 6, c = idx & 63;
        W_t[c][k] = W[k * FOUT + c];
    }
    // load 16 rows of h (coalesced)
    #pragma unroll
    for (int l = 0; l < 8; l++) {
        int idx = tid + l * 256;
        int r = idx >> 7, k = idx & 127;
        h_s[r][k] = h[(size_t)(row0 + r) * FIN + k];
    }
    __syncthreads();

    float acc[4] = {0.f, 0.f, 0.f, 0.f};
    #pragma unroll 4
    for (int k4 = 0; k4 < FIN; k4 += 4) {
        float4 w = *(const float4*)&W_t[fc][k4];
        #pragma unroll
        for (int r = 0; r < 4; r++) {
            float4 hv = *(const float4*)&h_s[rg * 4 + r][k4];
            acc[r] = fmaf(hv.x, w.x, acc[r]);
            acc[r] = fmaf(hv.y, w.y, acc[r]);
            acc[r] = fmaf(hv.z, w.z, acc[r]);
            acc[r] = fmaf(hv.w, w.w, acc[r]);
        }
    }

    float a1 = a[fc], a2 = a[FOUT + fc];
    float pf[4], pg[4];
    #pragma unroll
    for (int r = 0; r < 4; r++) {
        g_Wh[(size_t)(row0 + rg * 4 + r) * FOUT + fc] = acc[r];
        pf[r] = acc[r] * a1;
        pg[r] = acc[r] * a2;
    }
    #pragma unroll
    for (int off = 16; off > 0; off >>= 1) {
        #pragma unroll
        for (int r = 0; r < 4; r++) {
            pf[r] += __shfl_down_sync(0xffffffffu, pf[r], off);
            pg[r] += __shfl_down_sync(0xffffffffu, pg[r], off);
        }
    }
    int hb = (tid >> 5) & 1;      // which half of fc this warp covers
    if ((tid & 31) == 0) {
        #pragma unroll
        for (int r = 0; r < 4; r++) {
            red[rg * 4 + r][hb][0] = pf[r];
            red[rg * 4 + r][hb][1] = pg[r];
        }
    }
    __syncthreads();
    if (tid < 16) {
        g_f[row0 + tid] = red[tid][0][0] + red[tid][1][0];
        g_g[row0 + tid] = red[tid][0][1] + red[tid][1][1];
    }
}

// ---------------------------------------------------------------------------
// Kernel 2: fused masked-softmax attention + att@Wh (flash style, no max
// subtraction — exponent range is provably safe in fp32 for this problem).
// 512 threads, TI=64 rows, TJ=64 j-tile, 2 barriers per tile.
// Score mapping:  sr = tid>>3 (row), sq = tid&7 -> cols {4sq..4sq+3, 32+4sq..+3}
// Accum mapping:  c4 = (tid&15)*4 (4 cols), rg = tid>>4 -> rows {2rg, 2rg+1}
// ---------------------------------------------------------------------------
#define TI 64
#define TJ 64
#define THREADS 512
#define PSTR 68   // 272B rows: 16B aligned, conflict-free patterns

__global__ void __launch_bounds__(THREADS, 2) k_attn(const float* __restrict__ adj,
                                                     float* __restrict__ out) {
    __shared__ __align__(16) float Wh_s[TJ][PSTR];   // 17.4 KB
    __shared__ __align__(16) float p_s[TI][PSTR];    // 17.4 KB
    __shared__ float f_s[TI];
    __shared__ float rowsum[TI];

    int b   = blockIdx.y;
    int i0  = blockIdx.x * TI;
    int tid = threadIdx.x;

    int sr = tid >> 3;            // score row
    int sq = tid & 7;             // score quad pair
    int c4 = (tid & 15) * 4;      // accum cols
    int rg = tid >> 4;            // accum row group (0..31)

    const float* Wh_b = g_Wh + (size_t)b * N_ * FOUT;
    const float* gg_b = g_g + b * N_;
    const float* adj_r = adj + (size_t)(i0 + sr) * N_;

    if (tid < TI) {
        f_s[tid]    = g_f[b * N_ + i0 + tid];
        rowsum[tid] = 0.f;
    }
    __syncthreads();
    const float fi = f_s[sr];

    unsigned long long acc[2][2] = {{0ull, 0ull}, {0ull, 0ull}};

    // Wh-load mapping: pass l: idx = tid + 512*l -> (row = idx>>4, quad = idx&15)
    int wrow0 = tid >> 4,        wq0 = (tid & 15) * 4;
    int wrow1 = (tid + 512) >> 4, wq1 = wq0;

    for (int jt = 0; jt < N_ / TJ; jt++) {
        int j0 = jt * TJ;
        if (jt) __syncthreads();   // previous accumulate done with p_s / Wh_s

        // ---- issue Wh tile gmem loads early (overlap with score math) ----
        float4 wa = *(const float4*)&Wh_b[(size_t)(j0 + wrow0) * FOUT + wq0];
        float4 wb = *(const float4*)&Wh_b[(size_t)(j0 + wrow1) * FOUT + wq1];

        // ---- scores: p = adj>0 ? exp(lrelu(f_i + g_j)) : 0 ----
        float4 ad0 = *(const float4*)&adj_r[j0 + 4 * sq];
        float4 ad1 = *(const float4*)&adj_r[j0 + 32 + 4 * sq];
        float4 gv0 = *(const float4*)&gg_b[j0 + 4 * sq];
        float4 gv1 = *(const float4*)&gg_b[j0 + 32 + 4 * sq];

        float4 P0, P1;
        {
            float v;
            v = fi + gv0.x; v = fmaxf(v, ALPHA * v); P0.x = (ad0.x > 0.f) ? __expf(v) : 0.f;
            v = fi + gv0.y; v = fmaxf(v, ALPHA * v); P0.y = (ad0.y > 0.f) ? __expf(v) : 0.f;
            v = fi + gv0.z; v = fmaxf(v, ALPHA * v); P0.z = (ad0.z > 0.f) ? __expf(v) : 0.f;
            v = fi + gv0.w; v = fmaxf(v, ALPHA * v); P0.w = (ad0.w > 0.f) ? __expf(v) : 0.f;
            v = fi + gv1.x; v = fmaxf(v, ALPHA * v); P1.x = (ad1.x > 0.f) ? __expf(v) : 0.f;
            v = fi + gv1.y; v = fmaxf(v, ALPHA * v); P1.y = (ad1.y > 0.f) ? __expf(v) : 0.f;
            v = fi + gv1.z; v = fmaxf(v, ALPHA * v); P1.z = (ad1.z > 0.f) ? __expf(v) : 0.f;
            v = fi + gv1.w; v = fmaxf(v, ALPHA * v); P1.w = (ad1.w > 0.f) ? __expf(v) : 0.f;
        }
        *(float4*)&p_s[sr][4 * sq]      = P0;
        *(float4*)&p_s[sr][32 + 4 * sq] = P1;

        // rowsum partial: reduce 8 lanes covering this row
        float part = (P0.x + P0.y) + (P0.z + P0.w) + (P1.x + P1.y) + (P1.z + P1.w);
        part += __shfl_xor_sync(0xffffffffu, part, 1);
        part += __shfl_xor_sync(0xffffffffu, part, 2);
        part += __shfl_xor_sync(0xffffffffu, part, 4);
        if ((tid & 7) == 0) rowsum[sr] += part;

        // ---- park Wh tile in shared ----
        *(float4*)&Wh_s[wrow0][wq0] = wa;
        *(float4*)&Wh_s[wrow1][wq1] = wb;

        __syncthreads();

        // ---- accumulate: acc[r] += sum_j p[row][j] * Wh[j][c4..c4+3] ----
        const float* pr0 = p_s[rg * 2];
        const float* pr1 = p_s[rg * 2 + 1];
        #pragma unroll 4
        for (int jc = 0; jc < TJ; jc += 4) {
            ulonglong2 w0 = *(const ulonglong2*)&Wh_s[jc + 0][c4];
            ulonglong2 w1 = *(const ulonglong2*)&Wh_s[jc + 1][c4];
            ulonglong2 w2 = *(const ulonglong2*)&Wh_s[jc + 2][c4];
            ulonglong2 w3 = *(const ulonglong2*)&Wh_s[jc + 3][c4];
            float4 pv0 = *(const float4*)&pr0[jc];
            float4 pv1 = *(const float4*)&pr1[jc];

            unsigned long long pd;
            pd = pack2(pv0.x); acc[0][0] = fma2(pd, w0.x, acc[0][0]); acc[0][1] = fma2(pd, w0.y, acc[0][1]);
            pd = pack2(pv0.y); acc[0][0] = fma2(pd, w1.x, acc[0][0]); acc[0][1] = fma2(pd, w1.y, acc[0][1]);
            pd = pack2(pv0.z); acc[0][0] = fma2(pd, w2.x, acc[0][0]); acc[0][1] = fma2(pd, w2.y, acc[0][1]);
            pd = pack2(pv0.w); acc[0][0] = fma2(pd, w3.x, acc[0][0]); acc[0][1] = fma2(pd, w3.y, acc[0][1]);
            pd = pack2(pv1.x); acc[1][0] = fma2(pd, w0.x, acc[1][0]); acc[1][1] = fma2(pd, w0.y, acc[1][1]);
            pd = pack2(pv1.y); acc[1][0] = fma2(pd, w1.x, acc[1][0]); acc[1][1] = fma2(pd, w1.y, acc[1][1]);
            pd = pack2(pv1.z); acc[1][0] = fma2(pd, w2.x, acc[1][0]); acc[1][1] = fma2(pd, w2.y, acc[1][1]);
            pd = pack2(pv1.w); acc[1][0] = fma2(pd, w3.x, acc[1][0]); acc[1][1] = fma2(pd, w3.y, acc[1][1]);
        }
    }
    __syncthreads();   // all rowsum contributions landed

    float* out_b = out + (size_t)b * N_ * FOUT;
    #pragma unroll
    for (int r = 0; r < 2; r++) {
        int row = rg * 2 + r;
        float inv = 1.0f / rowsum[row];
        float2 v0 = *(float2*)&acc[r][0];
        float2 v1 = *(float2*)&acc[r][1];
        float4 o;
        o.x = v0.x * inv; o.y = v0.y * inv; o.z = v1.x * inv; o.w = v1.y * inv;
        *(float4*)&out_b[(size_t)(i0 + row) * FOUT + c4] = o;
    }
}

// ---------------------------------------------------------------------------
extern "C" void kernel_launch(void* const* d_in, const int* in_sizes, int n_in,
                              void* d_out, int out_size) {
    const float* h   = (const float*)d_in[0];
    const float* adj = (const float*)d_in[1];
    const float* W   = (const float*)d_in[2];
    const float* a   = (const float*)d_in[3];
    float* out = (float*)d_out;

    k_wh<<<(B_ * N_) / 16, 256>>>(h, W, a);

    dim3 grid(N_ / TI, B_);
    k_attn<<<grid, THREADS>>>(adj, out);
}

// round 5
// speedup vs baseline: 1.4654x; 1.2525x over previous
#include <cuda_runtime.h>
#include <cuda_bf16.h>

#define B_     8
#define N_     2048
#define FIN    128
#define FOUT   64
#define ALPHA  0.2f

// Scratch (device globals — no allocation allowed)
__device__ float g_Wh[B_ * N_ * FOUT];   // 4 MB
__device__ float g_f[B_ * N_];
__device__ float g_g[B_ * N_];

// ---------------------------------------------------------------------------
// packed fp32x2 helpers (sm_100+ PTX; ptxas never emits FFMA2 from C++)
// ---------------------------------------------------------------------------
__device__ __forceinline__ unsigned long long fma2(unsigned long long a,
                                                   unsigned long long b,
                                                   unsigned long long c) {
    unsigned long long d;
    asm("fma.rn.f32x2 %0, %1, %2, %3;" : "=l"(d) : "l"(a), "l"(b), "l"(c));
    return d;
}
__device__ __forceinline__ unsigned long long pack2(float p) {
    unsigned long long d;
    asm("mov.b64 %0, {%1, %1};" : "=l"(d) : "r"(__float_as_uint(p)));
    return d;
}
__device__ __forceinline__ unsigned smem_u32(const void* p) {
    return (unsigned)__cvta_generic_to_shared(p);
}
#define CP16(dst, src) \
    asm volatile("cp.async.cg.shared.global [%0], [%1], 16;" :: "r"(dst), "l"(src))

// ---------------------------------------------------------------------------
// Kernel 1: Wh = h @ W ; f = Wh @ a1 ; g = Wh @ a2
// ---------------------------------------------------------------------------
__global__ void __launch_bounds__(256) k_wh(const float* __restrict__ h,
                                            const float* __restrict__ W,
                                            const float* __restrict__ a) {
    __shared__ __align__(16) float W_t[FOUT][FIN + 4];
    __shared__ __align__(16) float h_s[16][FIN];
    __shared__ float red[16][2][2];

    int row0 = blockIdx.x * 16;
    int tid  = threadIdx.x;
    int fc   = tid & 63;
    int rg   = tid >> 6;

    #pragma unroll 8
    for (int l = 0; l < 32; l++) {
        int idx = tid + l * 256;
        int k = idx >> 6, c = idx & 63;
        W_t[c][k] = W[k * FOUT + c];
    }
    #pragma unroll
    for (int l = 0; l < 8; l++) {
        int idx = tid + l * 256;
        int r = idx >> 7, k = idx & 127;
        h_s[r][k] = h[(size_t)(row0 + r) * FIN + k];
    }
    __syncthreads();

    float acc[4] = {0.f, 0.f, 0.f, 0.f};
    #pragma unroll 4
    for (int k4 = 0; k4 < FIN; k4 += 4) {
        float4 w = *(const float4*)&W_t[fc][k4];
        #pragma unroll
        for (int r = 0; r < 4; r++) {
            float4 hv = *(const float4*)&h_s[rg * 4 + r][k4];
            acc[r] = fmaf(hv.x, w.x, acc[r]);
            acc[r] = fmaf(hv.y, w.y, acc[r]);
            acc[r] = fmaf(hv.z, w.z, acc[r]);
            acc[r] = fmaf(hv.w, w.w, acc[r]);
        }
    }

    float a1 = a[fc], a2 = a[FOUT + fc];
    float pf[4], pg[4];
    #pragma unroll
    for (int r = 0; r < 4; r++) {
        g_Wh[(size_t)(row0 + rg * 4 + r) * FOUT + fc] = acc[r];
        pf[r] = acc[r] * a1;
        pg[r] = acc[r] * a2;
    }
    #pragma unroll
    for (int off = 16; off > 0; off >>= 1) {
        #pragma unroll
        for (int r = 0; r < 4; r++) {
            pf[r] += __shfl_down_sync(0xffffffffu, pf[r], off);
            pg[r] += __shfl_down_sync(0xffffffffu, pg[r], off);
        }
    }
    int hb = (tid >> 5) & 1;
    if ((tid & 31) == 0) {
        #pragma unroll
        for (int r = 0; r < 4; r++) {
            red[rg * 4 + r][hb][0] = pf[r];
            red[rg * 4 + r][hb][1] = pg[r];
        }
    }
    __syncthreads();
    if (tid < 16) {
        g_f[row0 + tid] = red[tid][0][0] + red[tid][1][0];
        g_g[row0 + tid] = red[tid][0][1] + red[tid][1][1];
    }
}

// ---------------------------------------------------------------------------
// Kernel 2: fused masked-softmax attention + att@Wh (flash style; no max
// subtraction — exponent range provably safe in fp32 here).
// 128 threads, TI=64, TJ=64.
//  score mapping: sr = tid>>1 (row), cols (tid&1)*4 + 8k, k=0..7
//  accum mapping: cg = tid&7 -> cols 8cg..8cg+7 ; rg = tid>>3 -> rows
//                 {rg, rg+16, rg+32, rg+48}  (stride-16 keeps p-reads bank-clean)
// Wh_s uses a 16B-chunk XOR swizzle (q ^ bit3(q)) so the 8 per-warp w-reads
// (32B stride) land on all 32 banks -> 1 wavefront per LDS.128.
// ---------------------------------------------------------------------------
#define TI 64
#define TJ 64
#define TH 128
#define STR 68    // 272B row stride: 16B aligned; rows 1 apart -> +4 banks

__global__ void __launch_bounds__(TH, 5) k_attn(const float* __restrict__ adj,
                                                float* __restrict__ out) {
    __shared__ __align__(16) float Wh_s[TJ][STR];   // 17.4 KB
    __shared__ __align__(16) float p_s[TI][STR];    // 17.4 KB
    __shared__ float f_s[TI];
    __shared__ float rowsum[TI];

    int b   = blockIdx.y;
    int i0  = blockIdx.x * TI;
    int tid = threadIdx.x;

    int sr = tid >> 1;                 // score row
    int sq = (tid & 1) * 4;            // score col phase
    int cg = tid & 7;                  // accum col group (8 cols)
    int rg = tid >> 3;                 // accum row group (4 rows, stride 16)

    // swizzled 16B-chunk offsets for this thread's two w-chunks
    int oA = ((2 * cg)     ^ (((2 * cg)     >> 3) & 1)) * 4;
    int oB = ((2 * cg + 1) ^ (((2 * cg + 1) >> 3) & 1)) * 4;

    const float* Wh_b  = g_Wh + (size_t)b * N_ * FOUT;
    const float* gg    = g_g + b * N_;
    const float* adj_r = adj + (size_t)(i0 + sr) * N_;

    if (tid < TI) {
        f_s[tid]    = g_f[b * N_ + i0 + tid];
        rowsum[tid] = 0.f;
    }
    __syncthreads();
    const float fi = f_s[sr];

    unsigned long long acc[4][4];
    #pragma unroll
    for (int r = 0; r < 4; r++)
        #pragma unroll
        for (int c = 0; c < 4; c++) acc[r][c] = 0ull;

    for (int jt = 0; jt < N_ / TJ; jt++) {
        int j0 = jt * TJ;
        if (jt) __syncthreads();       // prev accumulate done with Wh_s / p_s

        // ---- async-copy Wh tile gmem->shared (swizzled), overlaps score ----
        #pragma unroll
        for (int l = 0; l < 8; l++) {
            int idx = tid + TH * l;            // 0..1023 16B chunks
            int row = idx >> 4, q = idx & 15;
            int qs = q ^ ((q >> 3) & 1);
            CP16(smem_u32(&Wh_s[row][qs * 4]),
                 &Wh_b[(size_t)(j0 + row) * FOUT + q * 4]);
        }

        // ---- scores: p = adj>0 ? exp(lrelu(f_i + g_j)) : 0 ----
        float part = 0.f;
        #pragma unroll
        for (int k = 0; k < 8; k++) {
            int c = sq + 8 * k;
            float4 ad = *(const float4*)&adj_r[j0 + c];
            float4 gv = *(const float4*)&gg[j0 + c];
            float4 P;
            float v;
            v = fi + gv.x; v = fmaxf(v, ALPHA * v); P.x = (ad.x > 0.f) ? __expf(v) : 0.f;
            v = fi + gv.y; v = fmaxf(v, ALPHA * v); P.y = (ad.y > 0.f) ? __expf(v) : 0.f;
            v = fi + gv.z; v = fmaxf(v, ALPHA * v); P.z = (ad.z > 0.f) ? __expf(v) : 0.f;
            v = fi + gv.w; v = fmaxf(v, ALPHA * v); P.w = (ad.w > 0.f) ? __expf(v) : 0.f;
            *(float4*)&p_s[sr][c] = P;
            part += (P.x + P.y) + (P.z + P.w);
        }
        part += __shfl_xor_sync(0xffffffffu, part, 1);
        if (!(tid & 1)) rowsum[sr] += part;

        asm volatile("cp.async.wait_all;" ::: "memory");
        __syncthreads();

        // ---- accumulate: acc[r][*] += p[row_r][j] * Wh[j][cols] ----
        #pragma unroll 2
        for (int jc = 0; jc < TJ; jc += 4) {
            float4 pv0 = *(const float4*)&p_s[rg     ][jc];
            float4 pv1 = *(const float4*)&p_s[rg + 16][jc];
            float4 pv2 = *(const float4*)&p_s[rg + 32][jc];
            float4 pv3 = *(const float4*)&p_s[rg + 48][jc];
            const float* pa0 = (const float*)&pv0;
            const float* pa1 = (const float*)&pv1;
            const float* pa2 = (const float*)&pv2;
            const float* pa3 = (const float*)&pv3;
            #pragma unroll
            for (int jj = 0; jj < 4; jj++) {
                ulonglong2 wA = *(const ulonglong2*)&Wh_s[jc + jj][oA];
                ulonglong2 wB = *(const ulonglong2*)&Wh_s[jc + jj][oB];
                unsigned long long pd;
                pd = pack2(pa0[jj]);
                acc[0][0] = fma2(pd, wA.x, acc[0][0]);
                acc[0][1] = fma2(pd, wA.y, acc[0][1]);
                acc[0][2] = fma2(pd, wB.x, acc[0][2]);
                acc[0][3] = fma2(pd, wB.y, acc[0][3]);
                pd = pack2(pa1[jj]);
                acc[1][0] = fma2(pd, wA.x, acc[1][0]);
                acc[1][1] = fma2(pd, wA.y, acc[1][1]);
                acc[1][2] = fma2(pd, wB.x, acc[1][2]);
                acc[1][3] = fma2(pd, wB.y, acc[1][3]);
                pd = pack2(pa2[jj]);
                acc[2][0] = fma2(pd, wA.x, acc[2][0]);
                acc[2][1] = fma2(pd, wA.y, acc[2][1]);
                acc[2][2] = fma2(pd, wB.x, acc[2][2]);
                acc[2][3] = fma2(pd, wB.y, acc[2][3]);
                pd = pack2(pa3[jj]);
                acc[3][0] = fma2(pd, wA.x, acc[3][0]);
                acc[3][1] = fma2(pd, wA.y, acc[3][1]);
                acc[3][2] = fma2(pd, wB.x, acc[3][2]);
                acc[3][3] = fma2(pd, wB.y, acc[3][3]);
            }
        }
    }
    __syncthreads();   // all rowsum contributions landed

    float* out_b = out + (size_t)b * N_ * FOUT;
    #pragma unroll
    for (int r = 0; r < 4; r++) {
        int row = rg + 16 * r;
        float inv = 1.0f / rowsum[row];
        float2 v0 = *(float2*)&acc[r][0];
        float2 v1 = *(float2*)&acc[r][1];
        float2 v2 = *(float2*)&acc[r][2];
        float2 v3 = *(float2*)&acc[r][3];
        float4 oa, ob;
        oa.x = v0.x * inv; oa.y = v0.y * inv; oa.z = v1.x * inv; oa.w = v1.y * inv;
        ob.x = v2.x * inv; ob.y = v2.y * inv; ob.z = v3.x * inv; ob.w = v3.y * inv;
        *(float4*)&out_b[(size_t)(i0 + row) * FOUT + 8 * cg]     = oa;
        *(float4*)&out_b[(size_t)(i0 + row) * FOUT + 8 * cg + 4] = ob;
    }
}

// ---------------------------------------------------------------------------
extern "C" void kernel_launch(void* const* d_in, const int* in_sizes, int n_in,
                              void* d_out, int out_size) {
    const float* h   = (const float*)d_in[0];
    const float* adj = (const float*)d_in[1];
    const float* W   = (const float*)d_in[2];
    const float* a   = (const float*)d_in[3];
    float* out = (float*)d_out;

    k_wh<<<(B_ * N_) / 16, 256>>>(h, W, a);

    dim3 grid(N_ / TI, B_);
    k_attn<<<grid, TH>>>(adj, out);
}